// round 15
// baseline (speedup 1.0000x reference)
#include <cuda_runtime.h>
#include <math.h>

// Problem constants
#define D_    32
#define H_    128
#define B_    64
#define T_    256
#define NSTEP 255
#define TOUT  252
#define NG    512          // 4 gates * 128
#define QKC   264          // 256 q/k cols + 4 vg cols + 4 pad
#define KREG  40           // phase1 weight k-slices in registers (float4 per k)
#define KSM   88           // phase1 weight k-slices in shared memory
#define HTS   20           // phase1 hT row stride (floats)
#define PS    268          // phase2 projection smem row stride (16B-aligned)
#define SCALE_ATTN 0.17677669529663688f
#define LOG2E_F 1.4426950408889634f

typedef unsigned long long u64;

// ---------------- device scratch ----------------
__device__ float d_Wcat2[D_ * H_ * H_ * 4];               // [d][k][h][gate j,i,f,o]
__device__ float d_Ucat2[D_ * H_ * 4];                    // [d][h][gate]
__device__ float d_Bcat2[D_ * H_ * 4];                    // [d][h][gate]
__device__ float d_qkT2[H_ * QKC];                        // [m][c]
__device__ float d_htraj[(size_t)NSTEP * D_ * B_ * H_];   // [t][d][b][h]

// ---------------- fast math helpers ----------------
__device__ __forceinline__ float fexp2a(float x) {
    float r; asm("ex2.approx.ftz.f32 %0, %1;" : "=f"(r) : "f"(x)); return r;
}
__device__ __forceinline__ float frcpa(float x) {
    float r; asm("rcp.approx.ftz.f32 %0, %1;" : "=f"(r) : "f"(x)); return r;
}
__device__ __forceinline__ float fsigmoid(float x) {
    return frcpa(1.f + fexp2a(-x * LOG2E_F));
}
__device__ __forceinline__ float ftanh(float x) {
    return fmaf(-2.f, frcpa(1.f + fexp2a(x * (2.f * LOG2E_F))), 1.f);
}
__device__ __forceinline__ void ffma2(u64& d, u64 a, u64 b) {
    asm("fma.rn.f32x2 %0, %1, %2, %0;" : "+l"(d) : "l"(a), "l"(b));
}
__device__ __forceinline__ u64 pack2(float w) {
    u64 r; asm("mov.b64 %0, {%1, %1};" : "=l"(r) : "f"(w)); return r;
}
__device__ __forceinline__ void unpack2(u64 v, float& lo, float& hi) {
    asm("mov.b64 {%0, %1}, %2;" : "=f"(lo), "=f"(hi) : "l"(v));
}

// ---------------- prep kernels ----------------
__global__ void prep_wcat2(const float* __restrict__ Wj, const float* __restrict__ Wi,
                           const float* __restrict__ Wf, const float* __restrict__ Wo) {
    int idx = blockIdx.x * 256 + threadIdx.x;            // total 32*128*128*4
    if (idx >= D_ * H_ * H_ * 4) return;
    int g = idx & 3, h = (idx >> 2) & 127, k = (idx >> 9) & 127, d = idx >> 16;
    const float* W = (g == 0) ? Wj : (g == 1) ? Wi : (g == 2) ? Wf : Wo;
    d_Wcat2[idx] = W[(d * H_ + k) * H_ + h];
}

__global__ void prep_ub2(const float* __restrict__ Uj, const float* __restrict__ Ui,
                         const float* __restrict__ Uf, const float* __restrict__ Uo,
                         const float* __restrict__ Bj, const float* __restrict__ Bi,
                         const float* __restrict__ Bf, const float* __restrict__ Bo) {
    int idx = blockIdx.x * 256 + threadIdx.x;            // total 32*128*4
    if (idx >= D_ * H_ * 4) return;
    int g = idx & 3, h = (idx >> 2) & 127, d = idx >> 9;
    const float* U = (g == 0) ? Uj : (g == 1) ? Ui : (g == 2) ? Uf : Uo;
    const float* Bp = (g == 0) ? Bj : (g == 1) ? Bi : (g == 2) ? Bf : Bo;
    d_Ucat2[idx] = U[d * H_ + h];
    d_Bcat2[idx] = Bp[d * H_ + h];
}

__global__ void prep_attn(const float* __restrict__ qkv_w, const float* __restrict__ out_w,
                          const float* __restrict__ h_proj_w, const float* __restrict__ w_p) {
    __shared__ float g_s[128];
    __shared__ float g2_s[128];
    int tid = threadIdx.x;  // = m
    float acc = 0.f;
    for (int n = 0; n < 128; n++) acc += h_proj_w[n * 128 + tid] * w_p[n];
    g_s[tid] = acc;
    __syncthreads();
    acc = 0.f;
    for (int hh = 0; hh < 128; hh++) acc += out_w[hh * 128 + tid] * g_s[hh];
    g2_s[tid] = acc;
    __syncthreads();
    for (int c = 0; c < 256; c++) d_qkT2[tid * QKC + c] = qkv_w[c * 128 + tid];
    for (int head = 0; head < 4; head++) {
        float a = 0.f;
        for (int hd = 0; hd < 32; hd++)
            a += qkv_w[(256 + head * 32 + hd) * 128 + tid] * g2_s[head * 32 + hd];
        d_qkT2[tid * QKC + 256 + head] = a;
    }
    for (int c = 260; c < QKC; c++) d_qkT2[tid * QKC + c] = 0.f;
}

// ---------------- phase 1: 255-step recurrence (proven R13 version, unchanged) ----------------
#define SM1_WSM 0
#define SM1_HT  (KSM * NG)
#define SM1_XS  (SM1_HT + 2 * H_ * HTS)
#define SM1_TOTAL (SM1_XS + NSTEP * 16)

#define FMA16(P0, P1, WJ, WI, WF, WO) \
    ffma2(aj[0], P0.x, WJ); ffma2(aj[1], P0.y, WJ); ffma2(aj[2], P1.x, WJ); ffma2(aj[3], P1.y, WJ); \
    ffma2(ai[0], P0.x, WI); ffma2(ai[1], P0.y, WI); ffma2(ai[2], P1.x, WI); ffma2(ai[3], P1.y, WI); \
    ffma2(af[0], P0.x, WF); ffma2(af[1], P0.y, WF); ffma2(af[2], P1.x, WF); ffma2(af[3], P1.y, WF); \
    ffma2(ao[0], P0.x, WO); ffma2(ao[1], P0.y, WO); ffma2(ao[2], P1.x, WO); ffma2(ao[3], P1.y, WO)

__global__ __launch_bounds__(256) void phase1(const float* __restrict__ x) {
    extern __shared__ __align__(16) float smem1[];
    float* wsm   = smem1 + SM1_WSM;
    float* hT    = smem1 + SM1_HT;
    float* xsall = smem1 + SM1_XS;

    int d  = blockIdx.x & 31;
    int bt = blockIdx.x >> 5;
    int b0 = bt * 16;
    int tid = threadIdx.x;
    int h  = tid & 127;
    int bg = tid >> 7;                 // batch group: batches bg*8 .. bg*8+7

    const float* Wd = d_Wcat2 + (size_t)d * H_ * H_ * 4;   // [k][h][gate]

    float4 wreg[KREG];
#pragma unroll
    for (int k = 0; k < KREG; k++) wreg[k] = *(const float4*)&Wd[(k * H_ + h) * 4];
    for (int i = tid; i < KSM * NG; i += 256) wsm[i] = Wd[KREG * NG + i];
    for (int i = tid; i < NSTEP * 16; i += 256) {
        int t = i >> 4, bb = i & 15;
        xsall[i] = x[((b0 + bb) * T_ + t) * D_ + d];
    }
    for (int i = tid; i < 2 * H_ * HTS; i += 256) hT[i] = 0.f;

    float4 u4    = *(const float4*)&d_Ucat2[(d * H_ + h) * 4];
    float4 bias4 = *(const float4*)&d_Bcat2[(d * H_ + h) * 4];
    float creg[8] = {0.f, 0.f, 0.f, 0.f, 0.f, 0.f, 0.f, 0.f};
    __syncthreads();                   // full barrier once: wsm/xsall/hT init

    int barid = 1 + bg;                // per-half named barrier id (1 or 2)

    for (int t = 0; t < NSTEP; t++) {
        int cur = t & 1, nxt = cur ^ 1;
        const float* hc = &hT[cur * H_ * HTS + bg * 8];

        u64 aj[4] = {0ull,0ull,0ull,0ull};
        u64 ai[4] = {0ull,0ull,0ull,0ull};
        u64 af[4] = {0ull,0ull,0ull,0ull};
        u64 ao[4] = {0ull,0ull,0ull,0ull};

#pragma unroll
        for (int k = 0; k < KREG; k++) {
            u64 wj = pack2(wreg[k].x), wi = pack2(wreg[k].y);
            u64 wf = pack2(wreg[k].z), wo = pack2(wreg[k].w);
            const ulonglong2* hp = (const ulonglong2*)&hc[k * HTS];
            ulonglong2 p0 = hp[0], p1 = hp[1];
            FMA16(p0, p1, wj, wi, wf, wo);
        }
#pragma unroll 8
        for (int kk = 0; kk < KSM; kk++) {
            float4 w4 = *(const float4*)&wsm[kk * NG + h * 4];
            u64 wj = pack2(w4.x), wi = pack2(w4.y), wf = pack2(w4.z), wo = pack2(w4.w);
            const ulonglong2* hp = (const ulonglong2*)&hc[(KREG + kk) * HTS];
            ulonglong2 p0 = hp[0], p1 = hp[1];
            FMA16(p0, p1, wj, wi, wf, wo);
        }

        const float* xs = &xsall[t * 16 + bg * 8];
        float* hw = &hT[nxt * H_ * HTS + h * HTS + bg * 8];
        size_t tb = (((size_t)t * D_ + d) * B_ + b0 + bg * 8) * H_ + h;
#pragma unroll
        for (int p = 0; p < 4; p++) {
            float j0, j1, i0, i1, f0, f1, o0, o1;
            unpack2(aj[p], j0, j1);
            unpack2(ai[p], i0, i1);
            unpack2(af[p], f0, f1);
            unpack2(ao[p], o0, o1);
            {
                float xv = xs[2 * p];
                float jj = ftanh(fmaf(xv, u4.x, j0 + bias4.x));
                float ii = fsigmoid(fmaf(xv, u4.y, i0 + bias4.y));
                float ff = fsigmoid(fmaf(xv, u4.z, f0 + bias4.z));
                float oo = fsigmoid(fmaf(xv, u4.w, o0 + bias4.w));
                creg[2 * p] = fmaf(creg[2 * p], ff, ii * jj);
                float hv = oo * ftanh(creg[2 * p]);
                hw[2 * p] = hv;
                d_htraj[tb + (size_t)(2 * p) * H_] = hv;
            }
            {
                float xv = xs[2 * p + 1];
                float jj = ftanh(fmaf(xv, u4.x, j1 + bias4.x));
                float ii = fsigmoid(fmaf(xv, u4.y, i1 + bias4.y));
                float ff = fsigmoid(fmaf(xv, u4.z, f1 + bias4.z));
                float oo = fsigmoid(fmaf(xv, u4.w, o1 + bias4.w));
                creg[2 * p + 1] = fmaf(creg[2 * p + 1], ff, ii * jj);
                float hv = oo * ftanh(creg[2 * p + 1]);
                hw[2 * p + 1] = hv;
                d_htraj[tb + (size_t)(2 * p + 1) * H_] = hv;
            }
        }
        // per-half barrier: only the 128 threads of this bg exchange through hT columns
        asm volatile("bar.sync %0, %1;" :: "r"(barid), "r"(128) : "memory");
    }
}

// ---------------- phase 2 (FUSED): projection GEMM -> smem -> attention -> pred ----------------
// Aliased smem (34.4 KB) + __launch_bounds__(288, 3) for 3 CTAs/SM (27 warps):
// the GEMM runs at 2.3x its fma floor due to latency exposure at 18 warps/SM.
// To fit the 75-reg cap, the attention epilogue uses ONLINE softmax (two passes
// over j, scores recomputed bit-identically in pass 2) -> no s[32] array.
#define SMF_TOTAL (32 * PS + 4)
__global__ __launch_bounds__(288, 3) void phase2(const float* __restrict__ b_p,
                                                 float* __restrict__ out) {
    extern __shared__ __align__(16) float smf[];
    float* hsT  = smf;              // [m][32 d], stride 36  (stage 1 only)
    float* psm  = smf;              // [d][PS]               (stage 2+, overwrites hsT)
    float* wsum = smf + 32 * PS;

    int b  = blockIdx.x;
    int tt = blockIdx.y;
    int t  = tt + 3;
    int tid = threadIdx.x;

    // 1. load h slab (float4 LDG, scalar transpose STS): (d, m) at src[d*B*H + m]
    const float* src = d_htraj + (((size_t)t * D_) * B_ + b) * H_;
    for (int i = tid; i < 32 * 32; i += 288) {       // 1024 float4
        int d = i >> 5, m4 = (i & 31) * 4;
        float4 v = __ldg((const float4*)&src[(size_t)d * B_ * H_ + m4]);
        hsT[(m4 + 0) * 36 + d] = v.x;
        hsT[(m4 + 1) * 36 + d] = v.y;
        hsT[(m4 + 2) * 36 + d] = v.z;
        hsT[(m4 + 3) * 36 + d] = v.w;
    }
    __syncthreads();

    // 2. projection GEMM: thread = 4 cols x 8 d-rows, accumulate fully in registers
    int cg = tid >> 2;               // 0..71, cols cg*4..cg*4+3 (active < 66)
    int rg = tid & 3;                // d-rows rg*8..rg*8+7
    u64 acc[16];
#pragma unroll
    for (int i = 0; i < 16; i++) acc[i] = 0ull;
    if (cg < 66) {
        int c0 = cg * 4;
        const float* hb = &hsT[rg * 8];
#pragma unroll 8
        for (int k = 0; k < H_; k++) {
            float4 w4 = __ldg((const float4*)&d_qkT2[k * QKC + c0]);
            const ulonglong2* hp = (const ulonglong2*)&hb[k * 36];
            ulonglong2 p0 = hp[0], p1 = hp[1];
            u64 w0 = pack2(w4.x), w1 = pack2(w4.y), w2 = pack2(w4.z), w3 = pack2(w4.w);
            ffma2(acc[0],  p0.x, w0); ffma2(acc[1],  p0.y, w0);
            ffma2(acc[2],  p1.x, w0); ffma2(acc[3],  p1.y, w0);
            ffma2(acc[4],  p0.x, w1); ffma2(acc[5],  p0.y, w1);
            ffma2(acc[6],  p1.x, w1); ffma2(acc[7],  p1.y, w1);
            ffma2(acc[8],  p0.x, w2); ffma2(acc[9],  p0.y, w2);
            ffma2(acc[10], p1.x, w2); ffma2(acc[11], p1.y, w2);
            ffma2(acc[12], p0.x, w3); ffma2(acc[13], p0.y, w3);
            ffma2(acc[14], p1.x, w3); ffma2(acc[15], p1.y, w3);
        }
    }
    __syncthreads();   // ALL threads done reading hsT -> safe to overwrite with psm

    if (cg < 66) {
        int c0 = cg * 4;
        float* dst = &psm[(rg * 8) * PS + c0];
#pragma unroll
        for (int rp = 0; rp < 4; rp++) {
            float v0l, v0h, v1l, v1h, v2l, v2h, v3l, v3h;
            unpack2(acc[rp],      v0l, v0h);
            unpack2(acc[4 + rp],  v1l, v1h);
            unpack2(acc[8 + rp],  v2l, v2h);
            unpack2(acc[12 + rp], v3l, v3h);
            *(float4*)&dst[(2 * rp) * PS]     = make_float4(v0l, v1l, v2l, v3l);
            *(float4*)&dst[(2 * rp + 1) * PS] = make_float4(v0h, v1h, v2h, v3h);
        }
    }
    __syncthreads();

    // 3. attention epilogue, warps 0-3 (head = warp, thread = query row i).
    //    Online softmax, scores recomputed in pass 2 (identical FFMA chains).
    if (tid < 128) {
        int head = tid >> 5, i = tid & 31;

        u64 q[16];
        {
            const ulonglong2* qp = (const ulonglong2*)&psm[i * PS + head * 32];
#pragma unroll
            for (int i2 = 0; i2 < 8; i2++) {
                ulonglong2 v = qp[i2];
                q[2 * i2]     = v.x;
                q[2 * i2 + 1] = v.y;
            }
        }

        // pass 1: online max + rescaled sum over j
        float m = -1e30f, ssum = 0.f;
#pragma unroll 4
        for (int j = 0; j < 32; j++) {
            const ulonglong2* kp = (const ulonglong2*)&psm[j * PS + 128 + head * 32];
            u64 sacc = 0ull;
#pragma unroll
            for (int i2 = 0; i2 < 8; i2++) {
                ulonglong2 kkv = kp[i2];
                ffma2(sacc, q[2 * i2],     kkv.x);
                ffma2(sacc, q[2 * i2 + 1], kkv.y);
            }
            float lo, hi;
            unpack2(sacc, lo, hi);
            float s = (lo + hi) * SCALE_ATTN;
            float mn = fmaxf(m, s);
            ssum = ssum * fexp2a((m - mn) * LOG2E_F) + fexp2a((s - mn) * LOG2E_F);
            m = mn;
        }
        float inv = frcpa(ssum);

        // pass 2: recompute scores, thresholded vg contraction
        float contrib = 0.f;
#pragma unroll 4
        for (int j = 0; j < 32; j++) {
            const ulonglong2* kp = (const ulonglong2*)&psm[j * PS + 128 + head * 32];
            u64 sacc = 0ull;
#pragma unroll
            for (int i2 = 0; i2 < 8; i2++) {
                ulonglong2 kkv = kp[i2];
                ffma2(sacc, q[2 * i2],     kkv.x);
                ffma2(sacc, q[2 * i2 + 1], kkv.y);
            }
            float lo, hi;
            unpack2(sacc, lo, hi);
            float s = (lo + hi) * SCALE_ATTN;
            float p = fexp2a((s - m) * LOG2E_F) * inv;
            float vgj = psm[j * PS + 256 + head];
            contrib += (p >= 0.01f) ? p * vgj : 0.f;
        }

#pragma unroll
        for (int off = 16; off; off >>= 1) contrib += __shfl_xor_sync(0xffffffffu, contrib, off);
        if (i == 0) wsum[head] = contrib;
    }
    __syncthreads();
    if (tid == 0)
        out[b * TOUT + tt] = (wsum[0] + wsum[1] + wsum[2] + wsum[3]) * (1.f / 32.f) + b_p[0];
}

// ---------------- launch ----------------
extern "C" void kernel_launch(void* const* d_in, const int* in_sizes, int n_in,
                              void* d_out, int out_size) {
    const float* x   = (const float*)d_in[0];
    const float* Uj  = (const float*)d_in[1];
    const float* Ui  = (const float*)d_in[2];
    const float* Uf  = (const float*)d_in[3];
    const float* Uo  = (const float*)d_in[4];
    const float* Wj  = (const float*)d_in[5];
    const float* Wi  = (const float*)d_in[6];
    const float* Wf  = (const float*)d_in[7];
    const float* Wo  = (const float*)d_in[8];
    const float* Bj  = (const float*)d_in[9];
    const float* Bi  = (const float*)d_in[10];
    const float* Bf  = (const float*)d_in[11];
    const float* Bo  = (const float*)d_in[12];
    // d_in[13..24] dead code
    const float* qkv_w    = (const float*)d_in[25];
    const float* out_w    = (const float*)d_in[26];
    const float* h_proj_w = (const float*)d_in[27];
    const float* w_p      = (const float*)d_in[28];
    const float* b_p      = (const float*)d_in[29];
    float* out = (float*)d_out;

    prep_wcat2<<<(D_ * H_ * H_ * 4 + 255) / 256, 256>>>(Wj, Wi, Wf, Wo);
    prep_ub2<<<(D_ * H_ * 4 + 255) / 256, 256>>>(Uj, Ui, Uf, Uo, Bj, Bi, Bf, Bo);
    prep_attn<<<1, 128>>>(qkv_w, out_w, h_proj_w, w_p);

    int smem1_bytes = SM1_TOTAL * 4;   // ~212 KB
    cudaFuncSetAttribute(phase1, cudaFuncAttributeMaxDynamicSharedMemorySize, smem1_bytes);
    phase1<<<128, 256, smem1_bytes>>>(x);

    int smf_bytes = SMF_TOTAL * 4;     // ~34.4 KB
    cudaFuncSetAttribute(phase2, cudaFuncAttributeMaxDynamicSharedMemorySize, smf_bytes);
    dim3 g2(B_, TOUT);
    phase2<<<g2, 288, smf_bytes>>>(b_p, out);
}

// round 17
// speedup vs baseline: 1.0477x; 1.0477x over previous
#include <cuda_runtime.h>
#include <math.h>

// Problem constants
#define D_    32
#define H_    128
#define B_    64
#define T_    256
#define NSTEP 255
#define TOUT  252
#define NG    512          // 4 gates * 128
#define QKC   264          // 256 q/k cols + 4 vg cols + 4 pad
#define KREG  40           // phase1 weight k-slices in registers (float4 per k)
#define KSM   88           // phase1 weight k-slices in shared memory
#define HTS   20           // phase1 hT row stride (floats)
#define PS    268          // phase2 projection smem row stride (16B-aligned)
#define SCALE_ATTN 0.17677669529663688f
#define LOG2E_F 1.4426950408889634f

typedef unsigned long long u64;

// ---------------- device scratch ----------------
__device__ float d_Wcat2[D_ * H_ * H_ * 4];               // [d][k][h][gate j,i,f,o]
__device__ float d_Ucat2[D_ * H_ * 4];                    // [d][h][gate]
__device__ float d_Bcat2[D_ * H_ * 4];                    // [d][h][gate]
__device__ float d_qkT2[H_ * QKC];                        // [m][c] (q-cols pre-scaled)
__device__ float d_htraj[(size_t)NSTEP * D_ * B_ * H_];   // [t][d][b][h]

// ---------------- fast math helpers ----------------
__device__ __forceinline__ float fexp2a(float x) {
    float r; asm("ex2.approx.ftz.f32 %0, %1;" : "=f"(r) : "f"(x)); return r;
}
__device__ __forceinline__ float frcpa(float x) {
    float r; asm("rcp.approx.ftz.f32 %0, %1;" : "=f"(r) : "f"(x)); return r;
}
__device__ __forceinline__ float fsigmoid(float x) {
    return frcpa(1.f + fexp2a(-x * LOG2E_F));
}
__device__ __forceinline__ float ftanh(float x) {
    return fmaf(-2.f, frcpa(1.f + fexp2a(x * (2.f * LOG2E_F))), 1.f);
}
__device__ __forceinline__ void ffma2(u64& d, u64 a, u64 b) {
    asm("fma.rn.f32x2 %0, %1, %2, %0;" : "+l"(d) : "l"(a), "l"(b));
}
__device__ __forceinline__ u64 pack2(float w) {
    u64 r; asm("mov.b64 %0, {%1, %1};" : "=l"(r) : "f"(w)); return r;
}
__device__ __forceinline__ void unpack2(u64 v, float& lo, float& hi) {
    asm("mov.b64 {%0, %1}, %2;" : "=f"(lo), "=f"(hi) : "l"(v));
}

// ---------------- prep kernels ----------------
__global__ void prep_wcat2(const float* __restrict__ Wj, const float* __restrict__ Wi,
                           const float* __restrict__ Wf, const float* __restrict__ Wo) {
    int idx = blockIdx.x * 256 + threadIdx.x;            // total 32*128*128*4
    if (idx >= D_ * H_ * H_ * 4) return;
    int g = idx & 3, h = (idx >> 2) & 127, k = (idx >> 9) & 127, d = idx >> 16;
    const float* W = (g == 0) ? Wj : (g == 1) ? Wi : (g == 2) ? Wf : Wo;
    d_Wcat2[idx] = W[(d * H_ + k) * H_ + h];
}

__global__ void prep_ub2(const float* __restrict__ Uj, const float* __restrict__ Ui,
                         const float* __restrict__ Uf, const float* __restrict__ Uo,
                         const float* __restrict__ Bj, const float* __restrict__ Bi,
                         const float* __restrict__ Bf, const float* __restrict__ Bo) {
    int idx = blockIdx.x * 256 + threadIdx.x;            // total 32*128*4
    if (idx >= D_ * H_ * 4) return;
    int g = idx & 3, h = (idx >> 2) & 127, d = idx >> 9;
    const float* U = (g == 0) ? Uj : (g == 1) ? Ui : (g == 2) ? Uf : Uo;
    const float* Bp = (g == 0) ? Bj : (g == 1) ? Bi : (g == 2) ? Bf : Bo;
    d_Ucat2[idx] = U[d * H_ + h];
    d_Bcat2[idx] = Bp[d * H_ + h];
}

// q-columns pre-multiplied by SCALE_ATTN: score = (q*scale) . k
__global__ void prep_attn(const float* __restrict__ qkv_w, const float* __restrict__ out_w,
                          const float* __restrict__ h_proj_w, const float* __restrict__ w_p) {
    __shared__ float g_s[128];
    __shared__ float g2_s[128];
    int tid = threadIdx.x;  // = m
    float acc = 0.f;
    for (int n = 0; n < 128; n++) acc += h_proj_w[n * 128 + tid] * w_p[n];
    g_s[tid] = acc;
    __syncthreads();
    acc = 0.f;
    for (int hh = 0; hh < 128; hh++) acc += out_w[hh * 128 + tid] * g_s[hh];
    g2_s[tid] = acc;
    __syncthreads();
    for (int c = 0; c < 256; c++)
        d_qkT2[tid * QKC + c] = qkv_w[c * 128 + tid] * (c < 128 ? SCALE_ATTN : 1.f);
    for (int head = 0; head < 4; head++) {
        float a = 0.f;
        for (int hd = 0; hd < 32; hd++)
            a += qkv_w[(256 + head * 32 + hd) * 128 + tid] * g2_s[head * 32 + hd];
        d_qkT2[tid * QKC + 256 + head] = a;
    }
    for (int c = 260; c < QKC; c++) d_qkT2[tid * QKC + c] = 0.f;
}

// ---------------- phase 1: 255-step recurrence (proven R13 version, unchanged) ----------------
#define SM1_WSM 0
#define SM1_HT  (KSM * NG)
#define SM1_XS  (SM1_HT + 2 * H_ * HTS)
#define SM1_TOTAL (SM1_XS + NSTEP * 16)

#define FMA16(P0, P1, WJ, WI, WF, WO) \
    ffma2(aj[0], P0.x, WJ); ffma2(aj[1], P0.y, WJ); ffma2(aj[2], P1.x, WJ); ffma2(aj[3], P1.y, WJ); \
    ffma2(ai[0], P0.x, WI); ffma2(ai[1], P0.y, WI); ffma2(ai[2], P1.x, WI); ffma2(ai[3], P1.y, WI); \
    ffma2(af[0], P0.x, WF); ffma2(af[1], P0.y, WF); ffma2(af[2], P1.x, WF); ffma2(af[3], P1.y, WF); \
    ffma2(ao[0], P0.x, WO); ffma2(ao[1], P0.y, WO); ffma2(ao[2], P1.x, WO); ffma2(ao[3], P1.y, WO)

__global__ __launch_bounds__(256) void phase1(const float* __restrict__ x) {
    extern __shared__ __align__(16) float smem1[];
    float* wsm   = smem1 + SM1_WSM;
    float* hT    = smem1 + SM1_HT;
    float* xsall = smem1 + SM1_XS;

    int d  = blockIdx.x & 31;
    int bt = blockIdx.x >> 5;
    int b0 = bt * 16;
    int tid = threadIdx.x;
    int h  = tid & 127;
    int bg = tid >> 7;                 // batch group: batches bg*8 .. bg*8+7

    const float* Wd = d_Wcat2 + (size_t)d * H_ * H_ * 4;   // [k][h][gate]

    float4 wreg[KREG];
#pragma unroll
    for (int k = 0; k < KREG; k++) wreg[k] = *(const float4*)&Wd[(k * H_ + h) * 4];
    for (int i = tid; i < KSM * NG; i += 256) wsm[i] = Wd[KREG * NG + i];
    for (int i = tid; i < NSTEP * 16; i += 256) {
        int t = i >> 4, bb = i & 15;
        xsall[i] = x[((b0 + bb) * T_ + t) * D_ + d];
    }
    for (int i = tid; i < 2 * H_ * HTS; i += 256) hT[i] = 0.f;

    float4 u4    = *(const float4*)&d_Ucat2[(d * H_ + h) * 4];
    float4 bias4 = *(const float4*)&d_Bcat2[(d * H_ + h) * 4];
    float creg[8] = {0.f, 0.f, 0.f, 0.f, 0.f, 0.f, 0.f, 0.f};
    __syncthreads();                   // full barrier once: wsm/xsall/hT init

    int barid = 1 + bg;                // per-half named barrier id (1 or 2)

    for (int t = 0; t < NSTEP; t++) {
        int cur = t & 1, nxt = cur ^ 1;
        const float* hc = &hT[cur * H_ * HTS + bg * 8];

        u64 aj[4] = {0ull,0ull,0ull,0ull};
        u64 ai[4] = {0ull,0ull,0ull,0ull};
        u64 af[4] = {0ull,0ull,0ull,0ull};
        u64 ao[4] = {0ull,0ull,0ull,0ull};

#pragma unroll
        for (int k = 0; k < KREG; k++) {
            u64 wj = pack2(wreg[k].x), wi = pack2(wreg[k].y);
            u64 wf = pack2(wreg[k].z), wo = pack2(wreg[k].w);
            const ulonglong2* hp = (const ulonglong2*)&hc[k * HTS];
            ulonglong2 p0 = hp[0], p1 = hp[1];
            FMA16(p0, p1, wj, wi, wf, wo);
        }
#pragma unroll 8
        for (int kk = 0; kk < KSM; kk++) {
            float4 w4 = *(const float4*)&wsm[kk * NG + h * 4];
            u64 wj = pack2(w4.x), wi = pack2(w4.y), wf = pack2(w4.z), wo = pack2(w4.w);
            const ulonglong2* hp = (const ulonglong2*)&hc[(KREG + kk) * HTS];
            ulonglong2 p0 = hp[0], p1 = hp[1];
            FMA16(p0, p1, wj, wi, wf, wo);
        }

        const float* xs = &xsall[t * 16 + bg * 8];
        float* hw = &hT[nxt * H_ * HTS + h * HTS + bg * 8];
        size_t tb = (((size_t)t * D_ + d) * B_ + b0 + bg * 8) * H_ + h;
#pragma unroll
        for (int p = 0; p < 4; p++) {
            float j0, j1, i0, i1, f0, f1, o0, o1;
            unpack2(aj[p], j0, j1);
            unpack2(ai[p], i0, i1);
            unpack2(af[p], f0, f1);
            unpack2(ao[p], o0, o1);
            {
                float xv = xs[2 * p];
                float jj = ftanh(fmaf(xv, u4.x, j0 + bias4.x));
                float ii = fsigmoid(fmaf(xv, u4.y, i0 + bias4.y));
                float ff = fsigmoid(fmaf(xv, u4.z, f0 + bias4.z));
                float oo = fsigmoid(fmaf(xv, u4.w, o0 + bias4.w));
                creg[2 * p] = fmaf(creg[2 * p], ff, ii * jj);
                float hv = oo * ftanh(creg[2 * p]);
                hw[2 * p] = hv;
                d_htraj[tb + (size_t)(2 * p) * H_] = hv;
            }
            {
                float xv = xs[2 * p + 1];
                float jj = ftanh(fmaf(xv, u4.x, j1 + bias4.x));
                float ii = fsigmoid(fmaf(xv, u4.y, i1 + bias4.y));
                float ff = fsigmoid(fmaf(xv, u4.z, f1 + bias4.z));
                float oo = fsigmoid(fmaf(xv, u4.w, o1 + bias4.w));
                creg[2 * p + 1] = fmaf(creg[2 * p + 1], ff, ii * jj);
                float hv = oo * ftanh(creg[2 * p + 1]);
                hw[2 * p + 1] = hv;
                d_htraj[tb + (size_t)(2 * p + 1) * H_] = hv;
            }
        }
        // per-half barrier: only the 128 threads of this bg exchange through hT columns
        asm volatile("bar.sync %0, %1;" :: "r"(barid), "r"(128) : "memory");
    }
}

// ---------------- phase 2 (FUSED): projection GEMM -> smem -> attention -> pred ----------------
// R13 base (separate hsT/psm, 2 CTAs/SM, unroll 8) + epilogue parallelized over
// 8 warps: warp = (head, j-half of 16), max/sum combined via smem partner exchange.
#define SMF_HST  0
#define SMF_PSM  (128 * 36)
#define SMF_MRED (SMF_PSM + 32 * PS)          // [8 warps][32 i]
#define SMF_SRED (SMF_MRED + 256)             // [8 warps][32 i]
#define SMF_CBUF (SMF_SRED + 256)             // [8]
#define SMF_TOTAL (SMF_CBUF + 8)
__global__ __launch_bounds__(288, 2) void phase2(const float* __restrict__ b_p,
                                                 float* __restrict__ out) {
    extern __shared__ __align__(16) float smf[];
    float* hsT  = smf + SMF_HST;    // [m][32 d], stride 36
    float* psm  = smf + SMF_PSM;    // [d][PS]
    float* mred = smf + SMF_MRED;
    float* sred = smf + SMF_SRED;
    float* cbuf = smf + SMF_CBUF;

    int b  = blockIdx.x;
    int tt = blockIdx.y;
    int t  = tt + 3;
    int tid = threadIdx.x;

    // 1. load h slab (float4 LDG, scalar transpose STS): (d, m) at src[d*B*H + m]
    const float* src = d_htraj + (((size_t)t * D_) * B_ + b) * H_;
    for (int i = tid; i < 32 * 32; i += 288) {       // 1024 float4
        int d = i >> 5, m4 = (i & 31) * 4;
        float4 v = __ldg((const float4*)&src[(size_t)d * B_ * H_ + m4]);
        hsT[(m4 + 0) * 36 + d] = v.x;
        hsT[(m4 + 1) * 36 + d] = v.y;
        hsT[(m4 + 2) * 36 + d] = v.z;
        hsT[(m4 + 3) * 36 + d] = v.w;
    }
    __syncthreads();

    // 2. projection GEMM: thread = 4 cols x 8 d-rows
    int cg = tid >> 2;               // 0..71, cols cg*4..cg*4+3 (active < 66)
    int rg = tid & 3;                // d-rows rg*8..rg*8+7
    if (cg < 66) {
        int c0 = cg * 4;
        u64 acc[16];
#pragma unroll
        for (int i = 0; i < 16; i++) acc[i] = 0ull;

        const float* hb = &hsT[rg * 8];
#pragma unroll 8
        for (int k = 0; k < H_; k++) {
            float4 w4 = __ldg((const float4*)&d_qkT2[k * QKC + c0]);
            const ulonglong2* hp = (const ulonglong2*)&hb[k * 36];
            ulonglong2 p0 = hp[0], p1 = hp[1];
            u64 w0 = pack2(w4.x), w1 = pack2(w4.y), w2 = pack2(w4.z), w3 = pack2(w4.w);
            ffma2(acc[0],  p0.x, w0); ffma2(acc[1],  p0.y, w0);
            ffma2(acc[2],  p1.x, w0); ffma2(acc[3],  p1.y, w0);
            ffma2(acc[4],  p0.x, w1); ffma2(acc[5],  p0.y, w1);
            ffma2(acc[6],  p1.x, w1); ffma2(acc[7],  p1.y, w1);
            ffma2(acc[8],  p0.x, w2); ffma2(acc[9],  p0.y, w2);
            ffma2(acc[10], p1.x, w2); ffma2(acc[11], p1.y, w2);
            ffma2(acc[12], p0.x, w3); ffma2(acc[13], p0.y, w3);
            ffma2(acc[14], p1.x, w3); ffma2(acc[15], p1.y, w3);
        }

        float* dst = &psm[(rg * 8) * PS + c0];
#pragma unroll
        for (int rp = 0; rp < 4; rp++) {
            float v0l, v0h, v1l, v1h, v2l, v2h, v3l, v3h;
            unpack2(acc[rp],      v0l, v0h);
            unpack2(acc[4 + rp],  v1l, v1h);
            unpack2(acc[8 + rp],  v2l, v2h);
            unpack2(acc[12 + rp], v3l, v3h);
            *(float4*)&dst[(2 * rp) * PS]     = make_float4(v0l, v1l, v2l, v3l);
            *(float4*)&dst[(2 * rp + 1) * PS] = make_float4(v0h, v1h, v2h, v3h);
        }
    }
    __syncthreads();

    // 3. attention epilogue, warps 0-7: warp w = (head = w>>1, j-half = w&1),
    //    thread = query row i. Scores pre-scaled (folded into q weights).
    int w    = tid >> 5;
    int act  = (tid < 256);
    int head = (w >> 1) & 3;
    int jh   = w & 1;
    int i    = tid & 31;
    int j0   = jh * 16;

    u64 q[16];
    float s[16];
    float mloc = -1e30f;
    if (act) {
        const ulonglong2* qp = (const ulonglong2*)&psm[i * PS + head * 32];
#pragma unroll
        for (int i2 = 0; i2 < 8; i2++) {
            ulonglong2 v = qp[i2];
            q[2 * i2]     = v.x;
            q[2 * i2 + 1] = v.y;
        }
#pragma unroll
        for (int jj = 0; jj < 16; jj++) {
            const ulonglong2* kp = (const ulonglong2*)&psm[(j0 + jj) * PS + 128 + head * 32];
            u64 sacc = 0ull;
#pragma unroll
            for (int i2 = 0; i2 < 8; i2++) {
                ulonglong2 kv = kp[i2];
                ffma2(sacc, q[2 * i2],     kv.x);
                ffma2(sacc, q[2 * i2 + 1], kv.y);
            }
            float lo, hi;
            unpack2(sacc, lo, hi);
            s[jj] = lo + hi;
            mloc = fmaxf(mloc, s[jj]);
        }
        mred[w * 32 + i] = mloc;
    }
    __syncthreads();

    float ssl = 0.f, m = 0.f;
    if (act) {
        m = fmaxf(mloc, mred[(w ^ 1) * 32 + i]);   // partner warp: same head, other half
#pragma unroll
        for (int jj = 0; jj < 16; jj++) {
            s[jj] = fexp2a((s[jj] - m) * LOG2E_F);
            ssl += s[jj];
        }
        sred[w * 32 + i] = ssl;
    }
    __syncthreads();

    if (act) {
        float inv = frcpa(ssl + sred[(w ^ 1) * 32 + i]);
        float contrib = 0.f;
#pragma unroll
        for (int jj = 0; jj < 16; jj++) {
            float p = s[jj] * inv;
            float vgj = psm[(j0 + jj) * PS + 256 + head];
            contrib += (p >= 0.01f) ? p * vgj : 0.f;
        }
#pragma unroll
        for (int off = 16; off; off >>= 1) contrib += __shfl_xor_sync(0xffffffffu, contrib, off);
        if (i == 0) cbuf[w] = contrib;
    }
    __syncthreads();
    if (tid == 0) {
        float tot = cbuf[0] + cbuf[1] + cbuf[2] + cbuf[3]
                  + cbuf[4] + cbuf[5] + cbuf[6] + cbuf[7];
        out[b * TOUT + tt] = tot * (1.f / 32.f) + b_p[0];
    }
}

// ---------------- launch ----------------
extern "C" void kernel_launch(void* const* d_in, const int* in_sizes, int n_in,
                              void* d_out, int out_size) {
    const float* x   = (const float*)d_in[0];
    const float* Uj  = (const float*)d_in[1];
    const float* Ui  = (const float*)d_in[2];
    const float* Uf  = (const float*)d_in[3];
    const float* Uo  = (const float*)d_in[4];
    const float* Wj  = (const float*)d_in[5];
    const float* Wi  = (const float*)d_in[6];
    const float* Wf  = (const float*)d_in[7];
    const float* Wo  = (const float*)d_in[8];
    const float* Bj  = (const float*)d_in[9];
    const float* Bi  = (const float*)d_in[10];
    const float* Bf  = (const float*)d_in[11];
    const float* Bo  = (const float*)d_in[12];
    // d_in[13..24] dead code
    const float* qkv_w    = (const float*)d_in[25];
    const float* out_w    = (const float*)d_in[26];
    const float* h_proj_w = (const float*)d_in[27];
    const float* w_p      = (const float*)d_in[28];
    const float* b_p      = (const float*)d_in[29];
    float* out = (float*)d_out;

    prep_wcat2<<<(D_ * H_ * H_ * 4 + 255) / 256, 256>>>(Wj, Wi, Wf, Wo);
    prep_ub2<<<(D_ * H_ * 4 + 255) / 256, 256>>>(Uj, Ui, Uf, Uo, Bj, Bi, Bf, Bo);
    prep_attn<<<1, 128>>>(qkv_w, out_w, h_proj_w, w_p);

    int smem1_bytes = SM1_TOTAL * 4;   // ~212 KB
    cudaFuncSetAttribute(phase1, cudaFuncAttributeMaxDynamicSharedMemorySize, smem1_bytes);
    phase1<<<128, 256, smem1_bytes>>>(x);

    int smf_bytes = SMF_TOTAL * 4;     // ~55 KB
    cudaFuncSetAttribute(phase2, cudaFuncAttributeMaxDynamicSharedMemorySize, smf_bytes);
    dim3 g2(B_, TOUT);
    phase2<<<g2, 288, smf_bytes>>>(b_p, out);
}